// round 8
// baseline (speedup 1.0000x reference)
#include <cuda_runtime.h>
#include <math_constants.h>

// Problem constants (fixed by the dataset: B=32, N=2048)
#define BATCH 32
#define NPTS  2048
#define TPB   256
#define NWARP (TPB / 32)           // 8 warps per block
#define BPB   16                   // blocks (chunks) per batch
#define ROWS  128                  // rows per block
#define GRID  (BATCH * BPB)        // 512
#define MRW   (NPTS / NWARP)       // m-range per warp = 256
#define RPL   4                    // rows per lane (32 lanes * 4 = 128 rows)
#define NG    (NPTS / 4)           // 512 groups of 4 points

__device__ double g_partial[GRID];
__device__ unsigned int g_count = 0;

typedef unsigned long long u64;

__device__ __forceinline__ u64 pack2(float lo, float hi) {
    u64 r;
    asm("mov.b64 %0, {%1, %2};" : "=l"(r) : "f"(lo), "f"(hi));
    return r;
}
__device__ __forceinline__ void unpack2(u64 v, float& lo, float& hi) {
    asm("mov.b64 {%0, %1}, %2;" : "=f"(lo), "=f"(hi) : "l"(v));
}
__device__ __forceinline__ u64 ffma2(u64 a, u64 b, u64 c) {
    u64 d;
    asm("fma.rn.f32x2 %0, %1, %2, %3;" : "=l"(d) : "l"(a), "l"(b), "l"(c));
    return d;
}

__device__ __forceinline__ void quat2mat(const float* __restrict__ q, float* R) {
    float w = q[0], x = q[1], y = q[2], z = q[3];
    float inv = 1.0f / sqrtf(w * w + x * x + y * y + z * z);
    w *= inv; x *= inv; y *= inv; z *= inv;
    R[0] = 1.f - 2.f * (y * y + z * z); R[1] = 2.f * (x * y - w * z); R[2] = 2.f * (x * z + w * y);
    R[3] = 2.f * (x * y + w * z);       R[4] = 1.f - 2.f * (x * x + z * z); R[5] = 2.f * (y * z - w * x);
    R[6] = 2.f * (x * z - w * y);       R[7] = 2.f * (y * z + w * x);       R[8] = 1.f - 2.f * (x * x + y * y);
}

__global__ void __launch_bounds__(TPB)
pts_loss_kernel(const float* __restrict__ q_est,
                const float* __restrict__ q_gt,
                const float* __restrict__ pts,
                const int*   __restrict__ sym,
                float* __restrict__ out)
{
    // Interleaved mapping: consecutive blocks -> different batches,
    // so sym work spreads evenly across SMs.
    const int b     = blockIdx.x % BATCH;
    const int chunk = blockIdx.x / BATCH;
    const int tid   = threadIdx.x;
    const int wid   = tid >> 5;
    const int lid   = tid & 31;

    // Interleaved SoA table: group g of 4 points stores
    // [x0..x3][y0..y3][z0..z3][w0..w3] in 64 contiguous bytes.
    // One base pointer per warp, 4 LDS.128 with immediate offsets per group.
    __shared__ __align__(16) float s_tab[NG * 16];
    __shared__ float s_min[NWARP][ROWS];   // per-warp partial mins
    __shared__ float s_xx[ROWS];
    __shared__ float red[TPB];

    float Re[9], Rg[9];
    quat2mat(q_est + 4 * b, Re);
    quat2mat(q_gt  + 4 * b, Rg);

    const float* __restrict__ P = pts + (size_t)b * NPTS * 3;
    const bool is_sym = (sym[b] != 0);

    float local = 0.0f;

    if (!is_sym) {
        // d_p path: ||(R_est - R_gt) @ p_n||^2, rows 0..127 on threads 0..127
        if (tid < ROWS) {
            float D[9];
            #pragma unroll
            for (int i = 0; i < 9; i++) D[i] = Re[i] - Rg[i];
            const int n = chunk * ROWS + tid;
            const float p0 = P[3 * n], p1 = P[3 * n + 1], p2 = P[3 * n + 2];
            const float e0 = D[0] * p0 + D[1] * p1 + D[2] * p2;
            const float e1 = D[3] * p0 + D[4] * p1 + D[5] * p2;
            const float e2 = D[6] * p0 + D[7] * p1 + D[8] * p2;
            local = e0 * e0 + e1 * e1 + e2 * e2;
        }
    } else {
        // Build interleaved y-table: (-2*y0, -2*y1, -2*y2, yy)
        for (int m = tid; m < NPTS; m += TPB) {
            const float p0 = P[3 * m], p1 = P[3 * m + 1], p2 = P[3 * m + 2];
            const float y0 = Rg[0] * p0 + Rg[1] * p1 + Rg[2] * p2;
            const float y1 = Rg[3] * p0 + Rg[4] * p1 + Rg[5] * p2;
            const float y2 = Rg[6] * p0 + Rg[7] * p1 + Rg[8] * p2;
            const int g = m >> 2, j = m & 3;
            float* t = s_tab + g * 16;
            t[j]      = -2.f * y0;
            t[j + 4]  = -2.f * y1;
            t[j + 8]  = -2.f * y2;
            t[j + 12] = y0 * y0 + y1 * y1 + y2 * y2;
        }
        __syncthreads();

        // Every warp covers ALL 128 rows (lane lid owns rows lid+32*r),
        // scanning only its m-eighth [wid*256, wid*256+256).
        u64 X0[RPL], X1[RPL], X2[RPL];
        float xxv[RPL];
        #pragma unroll
        for (int r = 0; r < RPL; r++) {
            const int n = chunk * ROWS + lid + 32 * r;
            const float p0 = P[3 * n], p1 = P[3 * n + 1], p2 = P[3 * n + 2];
            const float x0 = Re[0] * p0 + Re[1] * p1 + Re[2] * p2;
            const float x1 = Re[3] * p0 + Re[4] * p1 + Re[5] * p2;
            const float x2 = Re[6] * p0 + Re[7] * p1 + Re[8] * p2;
            X0[r] = pack2(x0, x0);
            X1[r] = pack2(x1, x1);
            X2[r] = pack2(x2, x2);
            xxv[r] = x0 * x0 + x1 * x1 + x2 * x2;
        }
        if (wid == 0) {
            #pragma unroll
            for (int r = 0; r < RPL; r++) s_xx[lid + 32 * r] = xxv[r];
        }

        float mn[RPL][4];
        #pragma unroll
        for (int r = 0; r < RPL; r++)
            #pragma unroll
            for (int k = 0; k < 4; k++) mn[r][k] = CUDART_INF_F;

        const float* __restrict__ base = s_tab + (wid * (MRW / 4)) * 16;

        #pragma unroll 4
        for (int g = 0; g < MRW / 4; g++) {
            const ulonglong2* __restrict__ q = (const ulonglong2*)(base + g * 16);
            const ulonglong2 vx = q[0];
            const ulonglong2 vy = q[1];
            const ulonglong2 vz = q[2];
            const ulonglong2 vw = q[3];
            #pragma unroll
            for (int r = 0; r < RPL; r++) {
                const u64 dA = ffma2(vx.x, X0[r], ffma2(vy.x, X1[r], ffma2(vz.x, X2[r], vw.x)));
                const u64 dB = ffma2(vx.y, X0[r], ffma2(vy.y, X1[r], ffma2(vz.y, X2[r], vw.y)));
                float a, c, d, e;
                unpack2(dA, a, c);   // register renaming, no SASS
                unpack2(dB, d, e);
                mn[r][0] = fminf(mn[r][0], a);
                mn[r][1] = fminf(mn[r][1], c);
                mn[r][2] = fminf(mn[r][2], d);
                mn[r][3] = fminf(mn[r][3], e);
            }
        }

        #pragma unroll
        for (int r = 0; r < RPL; r++)
            s_min[wid][lid + 32 * r] =
                fminf(fminf(mn[r][0], mn[r][1]), fminf(mn[r][2], mn[r][3]));
        __syncthreads();

        // Thread tid (<128) finalizes row tid: combine 8 warp partials + xx
        if (tid < ROWS) {
            float mm = s_min[0][tid];
            #pragma unroll
            for (int w = 1; w < NWARP; w++) mm = fminf(mm, s_min[w][tid]);
            local = s_xx[tid] + mm;
        }
    }

    // Deterministic block reduction
    red[tid] = local;
    __syncthreads();
    #pragma unroll
    for (int s = TPB / 2; s > 0; s >>= 1) {
        if (tid < s) red[tid] += red[tid + s];
        __syncthreads();
    }

    // Fused finalize: last block reduces all partials (fixed order -> deterministic)
    __shared__ bool is_last;
    if (tid == 0) {
        g_partial[blockIdx.x] = (double)red[0];
        __threadfence();
        unsigned int c = atomicAdd(&g_count, 1u);
        is_last = (c == GRID - 1);
    }
    __syncthreads();

    if (is_last) {
        __shared__ double sd[TPB];
        double acc = 0.0;
        #pragma unroll
        for (int i = 0; i < GRID / TPB; i++)
            acc += g_partial[tid + i * TPB];
        sd[tid] = acc;
        __syncthreads();
        #pragma unroll
        for (int s = TPB / 2; s > 0; s >>= 1) {
            if (tid < s) sd[tid] += sd[tid + s];
            __syncthreads();
        }
        if (tid == 0) {
            out[0] = (float)(sd[0] / (2.0 * (double)NPTS * (double)BATCH));
            g_count = 0;   // reset for next (graph-replayed) call
        }
    }
}

extern "C" void kernel_launch(void* const* d_in, const int* in_sizes, int n_in,
                              void* d_out, int out_size)
{
    // metadata order: q_est(32x4), q_gt(32x4), T(32x3, unused), pts(32x2048x3), symmetries(32x1 int32)
    const float* q_est = (const float*)d_in[0];
    const float* q_gt  = (const float*)d_in[1];
    const float* pts   = (const float*)d_in[3];
    const int*   sym   = (const int*)d_in[4];
    float* out = (float*)d_out;

    pts_loss_kernel<<<GRID, TPB>>>(q_est, q_gt, pts, sym, out);
}

// round 9
// speedup vs baseline: 1.0154x; 1.0154x over previous
#include <cuda_runtime.h>
#include <math_constants.h>

// Problem constants (fixed by the dataset: B=32, N=2048)
#define BATCH 32
#define NPTS  2048
#define TPB   256
#define NWARP (TPB / 32)            // 8 warps per block
#define CPB   32                    // row-chunks per batch
#define ROWS  64                    // rows per main block
#define GRID_MAIN (BATCH * CPB)     // 1024
#define GRID_PREP (BATCH * 8)       // 256 (8 blocks/batch, 256 pts each)
#define MRW   (NPTS / NWARP)        // m-range per warp = 256
#define GPW   (MRW / 4)             // 64 groups of 4 points per warp

__device__ float4 g_ytab[BATCH][NPTS];   // interleaved group layout (see prep)
__device__ float4 g_xtab[BATCH][NPTS];   // (x0, x1, x2, xx) per row
__device__ double g_partial[GRID_MAIN];
__device__ double g_prep[GRID_PREP];     // d_p partials (0 for sym batches)
__device__ unsigned int g_count = 0;

typedef unsigned long long u64;

__device__ __forceinline__ u64 pack2(float lo, float hi) {
    u64 r;
    asm("mov.b64 %0, {%1, %2};" : "=l"(r) : "f"(lo), "f"(hi));
    return r;
}
__device__ __forceinline__ void unpack2(u64 v, float& lo, float& hi) {
    asm("mov.b64 {%0, %1}, %2;" : "=f"(lo), "=f"(hi) : "l"(v));
}
__device__ __forceinline__ u64 ffma2(u64 a, u64 b, u64 c) {
    u64 d;
    asm("fma.rn.f32x2 %0, %1, %2, %3;" : "=l"(d) : "l"(a), "l"(b), "l"(c));
    return d;
}

__device__ __forceinline__ void quat2mat(const float* __restrict__ q, float* R) {
    float w = q[0], x = q[1], y = q[2], z = q[3];
    float inv = 1.0f / sqrtf(w * w + x * x + y * y + z * z);
    w *= inv; x *= inv; y *= inv; z *= inv;
    R[0] = 1.f - 2.f * (y * y + z * z); R[1] = 2.f * (x * y - w * z); R[2] = 2.f * (x * z + w * y);
    R[3] = 2.f * (x * y + w * z);       R[4] = 1.f - 2.f * (x * x + z * z); R[5] = 2.f * (y * z - w * x);
    R[6] = 2.f * (x * z - w * y);       R[7] = 2.f * (y * z + w * x);       R[8] = 1.f - 2.f * (x * x + y * y);
}

// ---------------------------------------------------------------------------
// Prep: per batch, build y-table (interleaved), x-table, and d_p for non-sym.
// grid = 256 blocks (8 per batch), 256 threads, 1 point per thread.
// ---------------------------------------------------------------------------
__global__ void __launch_bounds__(TPB)
prep_kernel(const float* __restrict__ q_est,
            const float* __restrict__ q_gt,
            const float* __restrict__ pts,
            const int*   __restrict__ sym)
{
    const int b   = blockIdx.x >> 3;
    const int seg = blockIdx.x & 7;
    const int tid = threadIdx.x;
    const int m   = seg * TPB + tid;

    float Re[9], Rg[9];
    quat2mat(q_est + 4 * b, Re);
    quat2mat(q_gt  + 4 * b, Rg);

    const float* __restrict__ P = pts + (size_t)b * NPTS * 3;
    const float p0 = P[3 * m], p1 = P[3 * m + 1], p2 = P[3 * m + 2];

    const float y0 = Rg[0] * p0 + Rg[1] * p1 + Rg[2] * p2;
    const float y1 = Rg[3] * p0 + Rg[4] * p1 + Rg[5] * p2;
    const float y2 = Rg[6] * p0 + Rg[7] * p1 + Rg[8] * p2;
    const float x0 = Re[0] * p0 + Re[1] * p1 + Re[2] * p2;
    const float x1 = Re[3] * p0 + Re[4] * p1 + Re[5] * p2;
    const float x2 = Re[6] * p0 + Re[7] * p1 + Re[8] * p2;

    // Interleaved group layout: group g = m/4, slot j = m%4:
    // floats [g*16+j]=-2y0, [g*16+4+j]=-2y1, [g*16+8+j]=-2y2, [g*16+12+j]=yy
    {
        float* yt = (float*)g_ytab[b];
        const int g = m >> 2, j = m & 3;
        yt[g * 16 + j]      = -2.f * y0;
        yt[g * 16 + 4 + j]  = -2.f * y1;
        yt[g * 16 + 8 + j]  = -2.f * y2;
        yt[g * 16 + 12 + j] = y0 * y0 + y1 * y1 + y2 * y2;
    }
    g_xtab[b][m] = make_float4(x0, x1, x2, x0 * x0 + x1 * x1 + x2 * x2);

    // d_p for non-sym batches (sym batches contribute 0 here)
    float dp = 0.0f;
    if (sym[b] == 0) {
        const float e0 = x0 - y0, e1 = x1 - y1, e2 = x2 - y2;
        dp = e0 * e0 + e1 * e1 + e2 * e2;
    }

    __shared__ float red[TPB];
    red[tid] = dp;
    __syncthreads();
    #pragma unroll
    for (int s = TPB / 2; s > 0; s >>= 1) {
        if (tid < s) red[tid] += red[tid + s];
        __syncthreads();
    }
    if (tid == 0) g_prep[blockIdx.x] = (double)red[0];
}

// ---------------------------------------------------------------------------
// Main: sym batches only do real work. Table copied L2 -> smem, then the
// all-pairs min scan with packed f32x2 FMAs and a 2-group software pipeline.
// ---------------------------------------------------------------------------
__global__ void __launch_bounds__(TPB)
pts_loss_kernel(const int* __restrict__ sym, float* __restrict__ out)
{
    const int b     = blockIdx.x % BATCH;   // interleaved: spreads sym work
    const int chunk = blockIdx.x / BATCH;
    const int tid   = threadIdx.x;
    const int wid   = tid >> 5;
    const int lid   = tid & 31;

    __shared__ __align__(16) float s_tab[NPTS * 4];   // 32 KB interleaved table
    __shared__ float s_min[NWARP][ROWS];
    __shared__ float s_xx[ROWS];
    __shared__ float red[TPB];

    float local = 0.0f;

    if (sym[b] != 0) {
        // Cooperative copy of the prebuilt table (8 x LDG.128 + STS.128 per thread)
        float4* s4 = (float4*)s_tab;
        const float4* __restrict__ src = g_ytab[b];
        #pragma unroll
        for (int i = 0; i < NPTS / TPB; i++)
            s4[tid + i * TPB] = src[tid + i * TPB];

        // This lane's two rows (precomputed x, xx)
        const float4 xa = g_xtab[b][chunk * ROWS + lid];
        const float4 xb = g_xtab[b][chunk * ROWS + lid + 32];
        __syncthreads();

        const u64 XA0 = pack2(xa.x, xa.x), XA1 = pack2(xa.y, xa.y), XA2 = pack2(xa.z, xa.z);
        const u64 XB0 = pack2(xb.x, xb.x), XB1 = pack2(xb.y, xb.y), XB2 = pack2(xb.z, xb.z);
        if (wid == 0) { s_xx[lid] = xa.w; s_xx[lid + 32] = xb.w; }

        float mA0 = CUDART_INF_F, mA1 = CUDART_INF_F, mA2 = CUDART_INF_F, mA3 = CUDART_INF_F;
        float mB0 = CUDART_INF_F, mB1 = CUDART_INF_F, mB2 = CUDART_INF_F, mB3 = CUDART_INF_F;

        const float* __restrict__ base = s_tab + wid * (GPW * 16);

        #pragma unroll 2
        for (int g = 0; g < GPW; g += 2) {
            // Front-batch both groups' loads (8 x LDS.128), then 40 math ops.
            const ulonglong2* __restrict__ q0 = (const ulonglong2*)(base + g * 16);
            const ulonglong2* __restrict__ q1 = (const ulonglong2*)(base + g * 16 + 16);
            const ulonglong2 vx0 = q0[0], vy0 = q0[1], vz0 = q0[2], vw0 = q0[3];
            const ulonglong2 vx1 = q1[0], vy1 = q1[1], vz1 = q1[2], vw1 = q1[3];

            float a, c, d, e;
            // group g, row A
            unpack2(ffma2(vx0.x, XA0, ffma2(vy0.x, XA1, ffma2(vz0.x, XA2, vw0.x))), a, c);
            unpack2(ffma2(vx0.y, XA0, ffma2(vy0.y, XA1, ffma2(vz0.y, XA2, vw0.y))), d, e);
            mA0 = fminf(mA0, a); mA1 = fminf(mA1, c); mA2 = fminf(mA2, d); mA3 = fminf(mA3, e);
            // group g, row B
            unpack2(ffma2(vx0.x, XB0, ffma2(vy0.x, XB1, ffma2(vz0.x, XB2, vw0.x))), a, c);
            unpack2(ffma2(vx0.y, XB0, ffma2(vy0.y, XB1, ffma2(vz0.y, XB2, vw0.y))), d, e);
            mB0 = fminf(mB0, a); mB1 = fminf(mB1, c); mB2 = fminf(mB2, d); mB3 = fminf(mB3, e);
            // group g+1, row A
            unpack2(ffma2(vx1.x, XA0, ffma2(vy1.x, XA1, ffma2(vz1.x, XA2, vw1.x))), a, c);
            unpack2(ffma2(vx1.y, XA0, ffma2(vy1.y, XA1, ffma2(vz1.y, XA2, vw1.y))), d, e);
            mA0 = fminf(mA0, a); mA1 = fminf(mA1, c); mA2 = fminf(mA2, d); mA3 = fminf(mA3, e);
            // group g+1, row B
            unpack2(ffma2(vx1.x, XB0, ffma2(vy1.x, XB1, ffma2(vz1.x, XB2, vw1.x))), a, c);
            unpack2(ffma2(vx1.y, XB0, ffma2(vy1.y, XB1, ffma2(vz1.y, XB2, vw1.y))), d, e);
            mB0 = fminf(mB0, a); mB1 = fminf(mB1, c); mB2 = fminf(mB2, d); mB3 = fminf(mB3, e);
        }

        s_min[wid][lid]      = fminf(fminf(mA0, mA1), fminf(mA2, mA3));
        s_min[wid][lid + 32] = fminf(fminf(mB0, mB1), fminf(mB2, mB3));
        __syncthreads();

        if (tid < ROWS) {
            float mm = s_min[0][tid];
            #pragma unroll
            for (int w = 1; w < NWARP; w++) mm = fminf(mm, s_min[w][tid]);
            local = s_xx[tid] + mm;
        }
    }

    // Deterministic block reduction
    red[tid] = local;
    __syncthreads();
    #pragma unroll
    for (int s = TPB / 2; s > 0; s >>= 1) {
        if (tid < s) red[tid] += red[tid + s];
        __syncthreads();
    }

    // Fused finalize: last block reduces all partials (fixed order -> deterministic)
    __shared__ bool is_last;
    if (tid == 0) {
        g_partial[blockIdx.x] = (double)red[0];
        __threadfence();
        unsigned int c = atomicAdd(&g_count, 1u);
        is_last = (c == GRID_MAIN - 1);
    }
    __syncthreads();

    if (is_last) {
        __shared__ double sd[TPB];
        double acc = 0.0;
        #pragma unroll
        for (int i = 0; i < GRID_MAIN / TPB; i++)
            acc += g_partial[tid + i * TPB];
        acc += g_prep[tid];               // GRID_PREP == TPB
        sd[tid] = acc;
        __syncthreads();
        #pragma unroll
        for (int s = TPB / 2; s > 0; s >>= 1) {
            if (tid < s) sd[tid] += sd[tid + s];
            __syncthreads();
        }
        if (tid == 0) {
            out[0] = (float)(sd[0] / (2.0 * (double)NPTS * (double)BATCH));
            g_count = 0;   // reset for next (graph-replayed) call
        }
    }
}

extern "C" void kernel_launch(void* const* d_in, const int* in_sizes, int n_in,
                              void* d_out, int out_size)
{
    // metadata order: q_est(32x4), q_gt(32x4), T(32x3, unused), pts(32x2048x3), symmetries(32x1 int32)
    const float* q_est = (const float*)d_in[0];
    const float* q_gt  = (const float*)d_in[1];
    const float* pts   = (const float*)d_in[3];
    const int*   sym   = (const int*)d_in[4];
    float* out = (float*)d_out;

    prep_kernel<<<GRID_PREP, TPB>>>(q_est, q_gt, pts, sym);
    pts_loss_kernel<<<GRID_MAIN, TPB>>>(sym, out);
}

// round 10
// speedup vs baseline: 1.0240x; 1.0084x over previous
#include <cuda_runtime.h>
#include <math_constants.h>

// Problem constants (fixed by the dataset: B=32, N=2048)
#define BATCH 32
#define NPTS  2048
#define TPB   256
#define NWARP (TPB / 32)            // 8 warps per block
#define CPB   32                    // row-chunks per batch
#define ROWS  64                    // rows per main block
#define GRID_MAIN (BATCH * CPB)     // 1024
#define GRID_PREP (BATCH * 8)       // 256 (8 blocks/batch, 256 pts each)
#define MRW   (NPTS / NWARP)        // m-range per warp = 256
#define GPW   (MRW / 4)             // 64 groups of 4 points per warp

__device__ float4 g_ytab[BATCH][NPTS];   // interleaved group layout (see prep)
__device__ float4 g_xtab[BATCH][NPTS];   // (x0, x1, x2, xx) per row
__device__ double g_partial[GRID_MAIN];
__device__ double g_prep[GRID_PREP];     // d_p partials (0 for sym batches)
__device__ unsigned int g_count = 0;

typedef unsigned long long u64;

__device__ __forceinline__ u64 pack2(float lo, float hi) {
    u64 r;
    asm("mov.b64 %0, {%1, %2};" : "=l"(r) : "f"(lo), "f"(hi));
    return r;
}
__device__ __forceinline__ void unpack2(u64 v, float& lo, float& hi) {
    asm("mov.b64 {%0, %1}, %2;" : "=f"(lo), "=f"(hi) : "l"(v));
}
__device__ __forceinline__ u64 ffma2(u64 a, u64 b, u64 c) {
    u64 d;
    asm("fma.rn.f32x2 %0, %1, %2, %3;" : "=l"(d) : "l"(a), "l"(b), "l"(c));
    return d;
}

__device__ __forceinline__ void quat2mat(const float* __restrict__ q, float* R) {
    float w = q[0], x = q[1], y = q[2], z = q[3];
    float inv = 1.0f / sqrtf(w * w + x * x + y * y + z * z);
    w *= inv; x *= inv; y *= inv; z *= inv;
    R[0] = 1.f - 2.f * (y * y + z * z); R[1] = 2.f * (x * y - w * z); R[2] = 2.f * (x * z + w * y);
    R[3] = 2.f * (x * y + w * z);       R[4] = 1.f - 2.f * (x * x + z * z); R[5] = 2.f * (y * z - w * x);
    R[6] = 2.f * (x * z - w * y);       R[7] = 2.f * (y * z + w * x);       R[8] = 1.f - 2.f * (x * x + y * y);
}

// ---------------------------------------------------------------------------
// Prep: per batch, build y-table (interleaved), x-table, and d_p for non-sym.
// grid = 256 blocks (8 per batch), 256 threads, 1 point per thread.
// ---------------------------------------------------------------------------
__global__ void __launch_bounds__(TPB)
prep_kernel(const float* __restrict__ q_est,
            const float* __restrict__ q_gt,
            const float* __restrict__ pts,
            const int*   __restrict__ sym)
{
    const int b   = blockIdx.x >> 3;
    const int seg = blockIdx.x & 7;
    const int tid = threadIdx.x;
    const int m   = seg * TPB + tid;

    float Re[9], Rg[9];
    quat2mat(q_est + 4 * b, Re);
    quat2mat(q_gt  + 4 * b, Rg);

    const float* __restrict__ P = pts + (size_t)b * NPTS * 3;
    const float p0 = P[3 * m], p1 = P[3 * m + 1], p2 = P[3 * m + 2];

    const float y0 = Rg[0] * p0 + Rg[1] * p1 + Rg[2] * p2;
    const float y1 = Rg[3] * p0 + Rg[4] * p1 + Rg[5] * p2;
    const float y2 = Rg[6] * p0 + Rg[7] * p1 + Rg[8] * p2;
    const float x0 = Re[0] * p0 + Re[1] * p1 + Re[2] * p2;
    const float x1 = Re[3] * p0 + Re[4] * p1 + Re[5] * p2;
    const float x2 = Re[6] * p0 + Re[7] * p1 + Re[8] * p2;

    // Interleaved group layout: group g = m/4, slot j = m%4:
    // floats [g*16+j]=-2y0, [g*16+4+j]=-2y1, [g*16+8+j]=-2y2, [g*16+12+j]=yy
    {
        float* yt = (float*)g_ytab[b];
        const int g = m >> 2, j = m & 3;
        yt[g * 16 + j]      = -2.f * y0;
        yt[g * 16 + 4 + j]  = -2.f * y1;
        yt[g * 16 + 8 + j]  = -2.f * y2;
        yt[g * 16 + 12 + j] = y0 * y0 + y1 * y1 + y2 * y2;
    }
    g_xtab[b][m] = make_float4(x0, x1, x2, x0 * x0 + x1 * x1 + x2 * x2);

    // d_p for non-sym batches (sym batches contribute 0 here)
    float dp = 0.0f;
    if (sym[b] == 0) {
        const float e0 = x0 - y0, e1 = x1 - y1, e2 = x2 - y2;
        dp = e0 * e0 + e1 * e1 + e2 * e2;
    }

    __shared__ float red[TPB];
    red[tid] = dp;
    __syncthreads();
    #pragma unroll
    for (int s = TPB / 2; s > 0; s >>= 1) {
        if (tid < s) red[tid] += red[tid + s];
        __syncthreads();
    }
    if (tid == 0) g_prep[blockIdx.x] = (double)red[0];
}

// ---------------------------------------------------------------------------
// Main: sym batches only do real work. Launched with PDL; waits on prep via
// cudaGridDependencySynchronize() before touching prep's outputs.
// ---------------------------------------------------------------------------
__global__ void __launch_bounds__(TPB)
pts_loss_kernel(const int* __restrict__ sym, float* __restrict__ out)
{
    const int b     = blockIdx.x % BATCH;   // interleaved: spreads sym work
    const int chunk = blockIdx.x / BATCH;
    const int tid   = threadIdx.x;
    const int wid   = tid >> 5;
    const int lid   = tid & 31;

    __shared__ __align__(16) float s_tab[NPTS * 4];   // 32 KB interleaved table
    __shared__ float s_min[NWARP][ROWS];
    __shared__ float s_xx[ROWS];
    __shared__ float red[TPB];

    // sym[] is a harness input (valid before prep) - safe to read pre-sync.
    const bool is_sym = (sym[b] != 0);

    // Wait for prep grid's writes (g_ytab, g_xtab, g_prep) to be visible.
    cudaGridDependencySynchronize();

    float local = 0.0f;

    if (is_sym) {
        // Cooperative copy of the prebuilt table (8 x LDG.128 + STS.128 per thread)
        float4* s4 = (float4*)s_tab;
        const float4* __restrict__ src = g_ytab[b];
        #pragma unroll
        for (int i = 0; i < NPTS / TPB; i++)
            s4[tid + i * TPB] = src[tid + i * TPB];

        // This lane's two rows (precomputed x, xx)
        const float4 xa = g_xtab[b][chunk * ROWS + lid];
        const float4 xb = g_xtab[b][chunk * ROWS + lid + 32];
        __syncthreads();

        const u64 XA0 = pack2(xa.x, xa.x), XA1 = pack2(xa.y, xa.y), XA2 = pack2(xa.z, xa.z);
        const u64 XB0 = pack2(xb.x, xb.x), XB1 = pack2(xb.y, xb.y), XB2 = pack2(xb.z, xb.z);
        if (wid == 0) { s_xx[lid] = xa.w; s_xx[lid + 32] = xb.w; }

        float mA0 = CUDART_INF_F, mA1 = CUDART_INF_F, mA2 = CUDART_INF_F, mA3 = CUDART_INF_F;
        float mB0 = CUDART_INF_F, mB1 = CUDART_INF_F, mB2 = CUDART_INF_F, mB3 = CUDART_INF_F;

        const float* __restrict__ base = s_tab + wid * (GPW * 16);

        #pragma unroll 2
        for (int g = 0; g < GPW; g += 2) {
            // Front-batch both groups' loads (8 x LDS.128), then 40 math ops.
            const ulonglong2* __restrict__ q0 = (const ulonglong2*)(base + g * 16);
            const ulonglong2* __restrict__ q1 = (const ulonglong2*)(base + g * 16 + 16);
            const ulonglong2 vx0 = q0[0], vy0 = q0[1], vz0 = q0[2], vw0 = q0[3];
            const ulonglong2 vx1 = q1[0], vy1 = q1[1], vz1 = q1[2], vw1 = q1[3];

            float a, c, d, e;
            // group g, row A
            unpack2(ffma2(vx0.x, XA0, ffma2(vy0.x, XA1, ffma2(vz0.x, XA2, vw0.x))), a, c);
            unpack2(ffma2(vx0.y, XA0, ffma2(vy0.y, XA1, ffma2(vz0.y, XA2, vw0.y))), d, e);
            mA0 = fminf(mA0, a); mA1 = fminf(mA1, c); mA2 = fminf(mA2, d); mA3 = fminf(mA3, e);
            // group g, row B
            unpack2(ffma2(vx0.x, XB0, ffma2(vy0.x, XB1, ffma2(vz0.x, XB2, vw0.x))), a, c);
            unpack2(ffma2(vx0.y, XB0, ffma2(vy0.y, XB1, ffma2(vz0.y, XB2, vw0.y))), d, e);
            mB0 = fminf(mB0, a); mB1 = fminf(mB1, c); mB2 = fminf(mB2, d); mB3 = fminf(mB3, e);
            // group g+1, row A
            unpack2(ffma2(vx1.x, XA0, ffma2(vy1.x, XA1, ffma2(vz1.x, XA2, vw1.x))), a, c);
            unpack2(ffma2(vx1.y, XA0, ffma2(vy1.y, XA1, ffma2(vz1.y, XA2, vw1.y))), d, e);
            mA0 = fminf(mA0, a); mA1 = fminf(mA1, c); mA2 = fminf(mA2, d); mA3 = fminf(mA3, e);
            // group g+1, row B
            unpack2(ffma2(vx1.x, XB0, ffma2(vy1.x, XB1, ffma2(vz1.x, XB2, vw1.x))), a, c);
            unpack2(ffma2(vx1.y, XB0, ffma2(vy1.y, XB1, ffma2(vz1.y, XB2, vw1.y))), d, e);
            mB0 = fminf(mB0, a); mB1 = fminf(mB1, c); mB2 = fminf(mB2, d); mB3 = fminf(mB3, e);
        }

        s_min[wid][lid]      = fminf(fminf(mA0, mA1), fminf(mA2, mA3));
        s_min[wid][lid + 32] = fminf(fminf(mB0, mB1), fminf(mB2, mB3));
        __syncthreads();

        if (tid < ROWS) {
            float mm = s_min[0][tid];
            #pragma unroll
            for (int w = 1; w < NWARP; w++) mm = fminf(mm, s_min[w][tid]);
            local = s_xx[tid] + mm;
        }
    }

    // Deterministic block reduction
    red[tid] = local;
    __syncthreads();
    #pragma unroll
    for (int s = TPB / 2; s > 0; s >>= 1) {
        if (tid < s) red[tid] += red[tid + s];
        __syncthreads();
    }

    // Fused finalize: last block reduces all partials (fixed order -> deterministic)
    __shared__ bool is_last;
    if (tid == 0) {
        g_partial[blockIdx.x] = (double)red[0];
        __threadfence();
        unsigned int c = atomicAdd(&g_count, 1u);
        is_last = (c == GRID_MAIN - 1);
    }
    __syncthreads();

    if (is_last) {
        __shared__ double sd[TPB];
        double acc = 0.0;
        #pragma unroll
        for (int i = 0; i < GRID_MAIN / TPB; i++)
            acc += g_partial[tid + i * TPB];
        acc += g_prep[tid];               // GRID_PREP == TPB
        sd[tid] = acc;
        __syncthreads();
        #pragma unroll
        for (int s = TPB / 2; s > 0; s >>= 1) {
            if (tid < s) sd[tid] += sd[tid + s];
            __syncthreads();
        }
        if (tid == 0) {
            out[0] = (float)(sd[0] / (2.0 * (double)NPTS * (double)BATCH));
            g_count = 0;   // reset for next (graph-replayed) call
        }
    }
}

extern "C" void kernel_launch(void* const* d_in, const int* in_sizes, int n_in,
                              void* d_out, int out_size)
{
    // metadata order: q_est(32x4), q_gt(32x4), T(32x3, unused), pts(32x2048x3), symmetries(32x1 int32)
    const float* q_est = (const float*)d_in[0];
    const float* q_gt  = (const float*)d_in[1];
    const float* pts   = (const float*)d_in[3];
    const int*   sym   = (const int*)d_in[4];
    float* out = (float*)d_out;

    prep_kernel<<<GRID_PREP, TPB>>>(q_est, q_gt, pts, sym);

    // Programmatic Dependent Launch: overlap main-kernel launch with prep.
    // The grid-dependency sync inside pts_loss_kernel enforces ordering.
    cudaLaunchConfig_t cfg = {};
    cfg.gridDim  = dim3(GRID_MAIN, 1, 1);
    cfg.blockDim = dim3(TPB, 1, 1);
    cfg.dynamicSmemBytes = 0;
    cfg.stream = 0;
    cudaLaunchAttribute attrs[1];
    attrs[0].id = cudaLaunchAttributeProgrammaticStreamSerialization;
    attrs[0].val.programmaticStreamSerializationAllowed = 1;
    cfg.attrs = attrs;
    cfg.numAttrs = 1;
    cudaLaunchKernelEx(&cfg, pts_loss_kernel, (const int*)sym, (float*)out);
}